// round 1
// baseline (speedup 1.0000x reference)
#include <cuda_runtime.h>

// Problem constants (fixed by the dataset): B=256, T=512, K=128
#define Bn 256
#define Tn 512
#define Kn 128

// Per-batch partial results (log_z - score). Device global scratch: no allocs.
__device__ float g_partial[Bn];

// One CTA per batch. 256 threads:
//   j    = tid & 127  -> state column this thread owns
//   half = tid >> 7   -> which half of the i-sum (i in [half*64, half*64+64))
// expT[:,j] for this thread's half lives in 64 registers.
__global__ __launch_bounds__(256, 2) void crf_forward_kernel(
    const float* __restrict__ logits,   // [B, T, K]
    const int*   __restrict__ labels,   // [B, T]
    const int*   __restrict__ seq_lens, // [B]
    const float* __restrict__ trans)    // [K, K]  trans[i*K + j], i=from, j=to
{
    __shared__ float sh_alpha[Kn];
    __shared__ float sh_aexp[Kn];
    __shared__ float sh_part[Kn];
    __shared__ float sh_wred[8];

    const int b    = blockIdx.x;
    const int tid  = threadIdx.x;
    const int j    = tid & (Kn - 1);
    const int half = tid >> 7;
    const int lane = tid & 31;
    const int warp = tid >> 5;

    const int   Tlen = seq_lens[b];            // 1..512, uniform across CTA
    const float* lg  = logits + (size_t)b * Tn * Kn;
    const int*   lb  = labels + b * Tn;

    // ---------------- gold-path score: unary + pairwise ----------------
    float sc = 0.f;
    for (int t = tid; t < Tlen; t += 256) {
        int y = lb[t];
        sc += lg[t * Kn + y];
        if (t >= 1) sc += trans[lb[t - 1] * Kn + y];
    }
    #pragma unroll
    for (int o = 16; o; o >>= 1) sc += __shfl_xor_sync(0xffffffffu, sc, o);
    if (lane == 0) sh_wred[warp] = sc;

    // ---------------- load expT column j (this half) into registers ----
    float eT[64];
    #pragma unroll
    for (int k = 0; k < 64; k++)
        eT[k] = __expf(trans[(half * 64 + k) * Kn + j]);   // coalesced over j

    // alpha_0 = logits[b, 0, :]
    if (tid < Kn) sh_alpha[j] = lg[j];
    __syncthreads();

    // fold the 8 per-warp score partials (fixed order -> deterministic)
    float score = 0.f;
    #pragma unroll
    for (int w = 0; w < 8; w++) score += sh_wred[w];
    __syncthreads();   // sh_wred reused by the scan loop below

    // prefetch logits for t=1 (safe: T dimension fully allocated)
    float logit_next = lg[Kn + j];

    // ---------------- forward recursion, only over unmasked steps ------
    for (int t = 1; t < Tlen; t++) {
        float lo = logit_next;
        int tn = (t + 1 < Tn) ? (t + 1) : t;          // in-bounds prefetch
        logit_next = lg[tn * Kn + j];

        // m = max_i alpha[i]  (warps 4..7 duplicate warps 0..3; harmless)
        float v = sh_alpha[j];
        #pragma unroll
        for (int o = 16; o; o >>= 1) v = fmaxf(v, __shfl_xor_sync(0xffffffffu, v, o));
        if (lane == 0) sh_wred[warp] = v;
        __syncthreads();
        float m = fmaxf(fmaxf(sh_wred[0], sh_wred[1]),
                        fmaxf(sh_wred[2], sh_wred[3]));

        if (tid < Kn) sh_aexp[j] = __expf(sh_alpha[j] - m);
        __syncthreads();

        // s_j(half) = sum_{i in half} aexp[i] * expT[i][j]   (64 reg-FMAs)
        const float4* ap = (const float4*)(sh_aexp + half * 64);
        float s0 = 0.f, s1 = 0.f, s2 = 0.f, s3 = 0.f;
        #pragma unroll
        for (int k = 0; k < 16; k++) {
            float4 a4 = ap[k];                         // smem broadcast
            s0 = fmaf(a4.x, eT[4 * k + 0], s0);
            s1 = fmaf(a4.y, eT[4 * k + 1], s1);
            s2 = fmaf(a4.z, eT[4 * k + 2], s2);
            s3 = fmaf(a4.w, eT[4 * k + 3], s3);
        }
        float s = (s0 + s1) + (s2 + s3);

        if (half) sh_part[j] = s;
        __syncthreads();
        if (tid < Kn) {
            float stot = s + sh_part[j];
            sh_alpha[j] = m + __logf(stot) + lo;       // new alpha
        }
        __syncthreads();
    }

    // ---------------- log_z = LSE(alpha_final) --------------------------
    {
        float v = sh_alpha[j];
        #pragma unroll
        for (int o = 16; o; o >>= 1) v = fmaxf(v, __shfl_xor_sync(0xffffffffu, v, o));
        if (lane == 0) sh_wred[warp] = v;
        __syncthreads();
        float m = fmaxf(fmaxf(sh_wred[0], sh_wred[1]),
                        fmaxf(sh_wred[2], sh_wred[3]));

        float e = (tid < Kn) ? __expf(sh_alpha[j] - m) : 0.f;
        #pragma unroll
        for (int o = 16; o; o >>= 1) e += __shfl_xor_sync(0xffffffffu, e, o);
        __syncthreads();                                // reuse sh_wred safely
        if (lane == 0) sh_wred[warp] = e;
        __syncthreads();

        if (tid == 0) {
            float stot = (sh_wred[0] + sh_wred[1]) + (sh_wred[2] + sh_wred[3]);
            float logz = m + __logf(stot);
            g_partial[b] = logz - score;               // per-batch NLL
        }
    }
}

// Deterministic final reduction: one block, fixed tree over 256 values.
__global__ void crf_reduce_kernel(float* __restrict__ out)
{
    __shared__ float sh[Bn];
    int t = threadIdx.x;
    sh[t] = g_partial[t];
    __syncthreads();
    #pragma unroll
    for (int s = Bn / 2; s > 0; s >>= 1) {
        if (t < s) sh[t] += sh[t + s];
        __syncthreads();
    }
    if (t == 0) out[0] = sh[0];
}

extern "C" void kernel_launch(void* const* d_in, const int* in_sizes, int n_in,
                              void* d_out, int out_size)
{
    const float* logits   = (const float*)d_in[0];
    const int*   labels   = (const int*)  d_in[1];
    const int*   seq_lens = (const int*)  d_in[2];
    const float* trans    = (const float*)d_in[3];
    float*       out      = (float*)d_out;

    crf_forward_kernel<<<Bn, 256>>>(logits, labels, seq_lens, trans);
    crf_reduce_kernel<<<1, Bn>>>(out);
}

// round 2
// speedup vs baseline: 1.5813x; 1.5813x over previous
#include <cuda_runtime.h>

// Problem constants (fixed by the dataset): B=256, T=512, K=128
#define Bn 256
#define Tn 512
#define Kn 128

// Per-batch partial results (log_z - score). Device global scratch: no allocs.
__device__ float g_partial[Bn];

// ---- packed f32x2 helpers (sm_103a FFMA2) ---------------------------------
__device__ __forceinline__ unsigned long long fma2(unsigned long long a,
                                                   unsigned long long b,
                                                   unsigned long long c) {
    unsigned long long d;
    asm("fma.rn.f32x2 %0, %1, %2, %3;" : "=l"(d) : "l"(a), "l"(b), "l"(c));
    return d;
}
__device__ __forceinline__ unsigned long long pack2(float lo, float hi) {
    unsigned long long d;
    asm("mov.b64 %0, {%1, %2};" : "=l"(d) : "f"(lo), "f"(hi));
    return d;
}
__device__ __forceinline__ float2 unpack2(unsigned long long v) {
    float lo, hi;
    asm("mov.b64 {%0, %1}, %2;" : "=f"(lo), "=f"(hi) : "l"(v));
    return make_float2(lo, hi);
}

// One CTA per batch, 128 threads. Thread j owns alpha[j] in a register and
// the full expT[:, j] column as 64 packed f32x2 register pairs.
// Per scan step: 1 exp, 1 smem store, 1 barrier, 32 LDS.128 (broadcast),
// 64 FFMA2, 1 log. Shift for LSE stability is a stale-by-one broadcast of
// alpha[0] (exactness of LSE does not depend on the shift; only overflow does,
// and the worst-case exponent arg is ~28 << 88).
__global__ __launch_bounds__(128, 2) void crf_forward_kernel(
    const float* __restrict__ logits,   // [B, T, K]
    const int*   __restrict__ labels,   // [B, T]
    const int*   __restrict__ seq_lens, // [B]
    const float* __restrict__ trans)    // [K, K] trans[i*K + j], i=from, j=to
{
    __shared__ __align__(16) float sh_aexp[2][Kn];
    __shared__ float sh_shift[2];
    __shared__ float sh_wred[4];

    const int b    = blockIdx.x;
    const int j    = threadIdx.x;        // 0..127
    const int lane = j & 31;
    const int warp = j >> 5;

    const int    Tlen = seq_lens[b];     // 1..512
    const float* lg   = logits + (size_t)b * Tn * Kn;
    const int*   lb   = labels + b * Tn;

    // ---------------- gold-path score: unary + pairwise ----------------
    float sc = 0.f;
    for (int t = j; t < Tlen; t += Kn) {
        int y = lb[t];
        sc += lg[t * Kn + y];
        if (t >= 1) sc += trans[lb[t - 1] * Kn + y];
    }
    #pragma unroll
    for (int o = 16; o; o >>= 1) sc += __shfl_xor_sync(0xffffffffu, sc, o);
    if (lane == 0) sh_wred[warp] = sc;

    // ---------------- expT column j, packed over i-pairs ----------------
    unsigned long long eT2[64];
    #pragma unroll
    for (int k = 0; k < 64; k++) {
        float e0 = __expf(trans[(2 * k)     * Kn + j]);   // coalesced in j
        float e1 = __expf(trans[(2 * k + 1) * Kn + j]);
        eT2[k] = pack2(e0, e1);
    }

    float alpha   = lg[j];          // alpha_0
    float shift   = 0.f;            // first-step shift; alpha_0 ~ N(0,1)
    float lo_next = lg[Kn + j];     // prefetch t=1 (T rows fully allocated)

    __syncthreads();
    const float score = (sh_wred[0] + sh_wred[1]) + (sh_wred[2] + sh_wred[3]);

    // ---------------- forward recursion (only unmasked steps) -----------
    int buf = 0;
    for (int t = 1; t < Tlen; t++) {
        float lo = lo_next;
        int   tn = (t + 1 < Tn) ? (t + 1) : t;
        lo_next  = lg[tn * Kn + j];

        sh_aexp[buf][j] = __expf(alpha - shift);
        if (j == 0) sh_shift[buf] = alpha;     // publish next shift
        __syncthreads();                       // the ONLY barrier per step
        const float nshift = sh_shift[buf];

        // s_j = sum_i aexp[i] * expT[i][j]  -- 64 packed FMAs, 4 chains
        const double2* ap = (const double2*)sh_aexp[buf];
        unsigned long long a0 = 0ull, a1 = 0ull, a2 = 0ull, a3 = 0ull;
        #pragma unroll
        for (int k = 0; k < 16; k++) {
            double2 x = ap[2 * k];             // LDS.128 broadcast
            double2 y = ap[2 * k + 1];
            a0 = fma2(__double_as_longlong(x.x), eT2[4 * k + 0], a0);
            a1 = fma2(__double_as_longlong(x.y), eT2[4 * k + 1], a1);
            a2 = fma2(__double_as_longlong(y.x), eT2[4 * k + 2], a2);
            a3 = fma2(__double_as_longlong(y.y), eT2[4 * k + 3], a3);
        }
        float2 p0 = unpack2(a0), p1 = unpack2(a1);
        float2 p2 = unpack2(a2), p3 = unpack2(a3);
        float s = ((p0.x + p0.y) + (p1.x + p1.y))
                + ((p2.x + p2.y) + (p3.x + p3.y));

        alpha = shift + __logf(s) + lo;
        shift = nshift;
        buf ^= 1;
    }

    // ---------------- log_z = LSE(alpha_final) --------------------------
    __syncthreads();                           // protect sh_wred reuse
    float v = alpha;
    #pragma unroll
    for (int o = 16; o; o >>= 1) v = fmaxf(v, __shfl_xor_sync(0xffffffffu, v, o));
    if (lane == 0) sh_wred[warp] = v;
    __syncthreads();
    const float m = fmaxf(fmaxf(sh_wred[0], sh_wred[1]),
                          fmaxf(sh_wred[2], sh_wred[3]));

    float e = __expf(alpha - m);
    #pragma unroll
    for (int o = 16; o; o >>= 1) e += __shfl_xor_sync(0xffffffffu, e, o);
    __syncthreads();                           // all reads of m done
    if (lane == 0) sh_wred[warp] = e;
    __syncthreads();

    if (j == 0) {
        float stot = (sh_wred[0] + sh_wred[1]) + (sh_wred[2] + sh_wred[3]);
        g_partial[b] = m + __logf(stot) - score;   // per-batch NLL
    }
}

// Deterministic final reduction: one warp, fixed tree over 256 values.
__global__ void crf_reduce_kernel(float* __restrict__ out)
{
    int lane = threadIdx.x;        // 32 threads
    float s = 0.f;
    #pragma unroll
    for (int k = 0; k < 8; k++)    // fixed order: deterministic
        s += g_partial[lane + 32 * k];
    #pragma unroll
    for (int o = 16; o; o >>= 1) s += __shfl_xor_sync(0xffffffffu, s, o);
    if (lane == 0) out[0] = s;
}

extern "C" void kernel_launch(void* const* d_in, const int* in_sizes, int n_in,
                              void* d_out, int out_size)
{
    const float* logits   = (const float*)d_in[0];
    const int*   labels   = (const int*)  d_in[1];
    const int*   seq_lens = (const int*)  d_in[2];
    const float* trans    = (const float*)d_in[3];
    float*       out      = (float*)d_out;

    crf_forward_kernel<<<Bn, 128>>>(logits, labels, seq_lens, trans);
    crf_reduce_kernel<<<1, 32>>>(out);
}